// round 16
// baseline (speedup 1.0000x reference)
#include <cuda_runtime.h>
#include <cuda_fp16.h>
#include <cstdint>

#define NB    32
#define CIN   64
#define COUT  128
#define HDIM  64
#define WDIM  64
#define EPSV  1e-8f
#define FM_OFF (NB * COUT * HDIM * WDIM)
#define NTILES 32768              // 32 n * 32 ty * 32 tx (2x2 output tiles)
#define NTB    2048               // tile blocks of 16

// ---- scratch (static __device__, no allocations) ----
__device__ float g_inv_norm[COUT];
// A operand, MMA-fragment-packed: [pos][tileblk][kb][lane][8 halves]
__device__ __align__(128) __half gAh_f[16][NTB][4][32][8];
__device__ __align__(128) __half gAl_f[16][NTB][4][32][8];
// B operand, fragment-packed: [pos][kb][n8blk][lane][4 halves]
__device__ __align__(128) __half gBh_f[16][4][16][32][4];
__device__ __align__(128) __half gBl_f[16][4][16][32][4];

__device__ __forceinline__ void mma16(float* d, uint32_t a0, uint32_t a1,
                                      uint32_t a2, uint32_t a3, uint32_t b0,
                                      uint32_t b1) {
    asm volatile(
        "mma.sync.aligned.m16n8k16.row.col.f32.f16.f16.f32 "
        "{%0,%1,%2,%3},{%4,%5,%6,%7},{%8,%9},{%0,%1,%2,%3};"
        : "+f"(d[0]), "+f"(d[1]), "+f"(d[2]), "+f"(d[3])
        : "r"(a0), "r"(a1), "r"(a2), "r"(a3), "r"(b0), "r"(b1));
}

// output transform rows A^T = {{1,1,1,0},{0,1,-1,-1}}
__device__ const float cA0[4] = {1.f, 1.f, 1.f, 0.f};
__device__ const float cA1[4] = {0.f, 1.f, -1.f, -1.f};

// ---------- prep: per-Cout 1/(||k||^2 + eps) ----------
__global__ void prep_norm(const float* __restrict__ kern) {
    __shared__ float red[512];
    int t = threadIdx.x;
    int co = t & 127;
    int part = t >> 7;
    float s = 0.f;
#pragma unroll 4
    for (int i = part * 144; i < part * 144 + 144; i++) {
        float v = kern[i * COUT + co];
        s += v * v;
    }
    red[t] = s;
    __syncthreads();
    if (t < 128)
        g_inv_norm[co] = 1.f / (red[co] + red[co + 128] + red[co + 256] + red[co + 384] + EPSV);
}

// ---------- prep: weight transform W~ = G g G^T, fragment-packed fp16 hi/lo ----------
__global__ void prep_Wt(const float* __restrict__ kern) {
    int id = blockIdx.x * 256 + threadIdx.x;   // 8192
    int co = id & 127;
    int ci = id >> 7;

    float g[3][3];
#pragma unroll
    for (int kh = 0; kh < 3; kh++)
#pragma unroll
        for (int kw = 0; kw < 3; kw++)
            g[kh][kw] = kern[(kh * 3 + kw) * (CIN * COUT) + ci * COUT + co];

    float t[4][3];
#pragma unroll
    for (int kw = 0; kw < 3; kw++) {
        t[0][kw] = g[0][kw];
        t[1][kw] = 0.5f * (g[0][kw] + g[1][kw] + g[2][kw]);
        t[2][kw] = 0.5f * (g[0][kw] - g[1][kw] + g[2][kw]);
        t[3][kw] = g[2][kw];
    }
    const int kb = ci >> 4;
    const int ihalf = (ci >> 3) & 1;
    const int tig = (ci >> 1) & 3;
    const int lsb = ci & 1;
    const int L = (co & 7) * 4 + tig;
    const int nb = co >> 3;
#pragma unroll
    for (int i = 0; i < 4; i++) {
        float wv[4];
        wv[0] = t[i][0];
        wv[1] = 0.5f * (t[i][0] + t[i][1] + t[i][2]);
        wv[2] = 0.5f * (t[i][0] - t[i][1] + t[i][2]);
        wv[3] = t[i][2];
#pragma unroll
        for (int j = 0; j < 4; j++) {
            int p = i * 4 + j;
            __half h = __float2half(wv[j]);
            __half l = __float2half(wv[j] - __half2float(h));
            gBh_f[p][kb][nb][L][ihalf * 2 + lsb] = h;
            gBl_f[p][kb][nb][L][ihalf * 2 + lsb] = l;
        }
    }
}

// ---------- prep: input transform X~ = B^T d B, fragment-packed via smem ----------
#define XT_SMEM ((8976 + 2 * 576) * 4)
__global__ __launch_bounds__(512)
void prep_Xt(const float* __restrict__ x) {
    extern __shared__ float xs[];
    uint32_t* st0 = (uint32_t*)&xs[8976];
    uint32_t* st1 = st0 + 576;

    const int txh = blockIdx.x & 1;
    const int ty = (blockIdx.x >> 1) & 31;
    const int n = blockIdx.x >> 6;
    const int tid = threadIdx.x;
    const int txl = tid >> 5;         // 0..15
    const int cp = tid & 31;          // ci pair

    // slab load: 64ci x 4r x 34c (halo cols txh*32-1 .. txh*32+32)
#pragma unroll 1
    for (int idx = tid; idx < 8704; idx += 512) {
        int ci = idx / 136;
        int rem = idx - ci * 136;
        int r = rem / 34;
        int c = rem - r * 34;
        int gr = 2 * ty - 1 + r;
        int gc = txh * 32 - 1 + c;
        float v = 0.f;
        if (gr >= 0 && gr < HDIM && gc >= 0 && gc < WDIM)
            v = __ldg(x + ((n * CIN + ci) * HDIM + gr) * WDIM + gc);
        xs[(r * 34 + c) * 66 + ci] = v;
    }
    __syncthreads();

    float2 s[4][4];
    {
        float2 d[4][4];
#pragma unroll
        for (int c = 0; c < 4; c++) {
            int cl = 2 * txl + c;
#pragma unroll
            for (int r = 0; r < 4; r++)
                d[r][c] = *(const float2*)&xs[(r * 34 + cl) * 66 + 2 * cp];
        }
#pragma unroll
        for (int c = 0; c < 4; c++) {
            s[0][c].x = d[0][c].x - d[2][c].x;  s[0][c].y = d[0][c].y - d[2][c].y;
            s[1][c].x = d[1][c].x + d[2][c].x;  s[1][c].y = d[1][c].y + d[2][c].y;
            s[2][c].x = d[2][c].x - d[1][c].x;  s[2][c].y = d[2][c].y - d[1][c].y;
            s[3][c].x = d[1][c].x - d[3][c].x;  s[3][c].y = d[1][c].y - d[3][c].y;
        }
    }

    const int tb = n * 64 + ty * 2 + txh;

#pragma unroll 1
    for (int p = 0; p < 16; p++) {
        const int i = p >> 2, j = p & 3;
        float vx, vy;
        if (j == 0)      { vx = s[i][0].x - s[i][2].x; vy = s[i][0].y - s[i][2].y; }
        else if (j == 1) { vx = s[i][1].x + s[i][2].x; vy = s[i][1].y + s[i][2].y; }
        else if (j == 2) { vx = s[i][2].x - s[i][1].x; vy = s[i][2].y - s[i][1].y; }
        else             { vx = s[i][1].x - s[i][3].x; vy = s[i][1].y - s[i][3].y; }

        __half hx = __float2half(vx);
        __half lx = __float2half(vx - __half2float(hx));
        __half hy = __float2half(vy);
        __half ly = __float2half(vy - __half2float(hy));
        st0[txl * 36 + cp] = (uint32_t)__half_as_ushort(hx) |
                             ((uint32_t)__half_as_ushort(hy) << 16);
        st1[txl * 36 + cp] = (uint32_t)__half_as_ushort(lx) |
                             ((uint32_t)__half_as_ushort(ly) << 16);
        __syncthreads();

        if (tid < 256) {
            const int pl = tid >> 7;
            const int rem = tid & 127;
            const int kb = rem >> 5;
            const int L = rem & 31;
            const uint32_t* stp = pl ? st1 : st0;
            int tl = L >> 2, cc = kb * 8 + (L & 3);
            uint4 val;
            val.x = stp[tl * 36 + cc];
            val.y = stp[(tl + 8) * 36 + cc];
            val.z = stp[tl * 36 + cc + 4];
            val.w = stp[(tl + 8) * 36 + cc + 4];
            if (pl == 0)
                *(uint4*)&gAh_f[p][tb][kb][L][0] = val;
            else
                *(uint4*)&gAl_f[p][tb][kb][L][0] = val;
        }
        __syncthreads();
    }
}

// ---------- main: HMMA fp16x3 Winograd GEMM, fragment-direct LDG ----------
__global__ __launch_bounds__(256, 2)
void wino_gemm(const float* __restrict__ mem, const float* __restrict__ beta_p,
               const float* __restrict__ b_p, float* __restrict__ out) {
    __shared__ float snorm[64], sb[64];

    const int tid = threadIdx.x;
    const int lane = tid & 31;
    const int wrp = tid >> 5;
    const int mw = wrp & 3;           // M-warp: tiles mw*16..+15
    const int nw = wrp >> 2;          // N-warp: co nw*32..+31
    const int bid = blockIdx.x;
    const int chalf = bid & 1;
    const int TB = (bid >> 1) * 64;   // base tile

    if (tid < 64) {
        snorm[tid] = g_inv_norm[chalf * 64 + tid];
        sb[tid] = b_p[chalf * 64 + tid];
    }
    __syncthreads();

    float acc[4][16];
#pragma unroll
    for (int q = 0; q < 4; q++)
#pragma unroll
        for (int i = 0; i < 16; i++) acc[q][i] = 0.f;

    const int tbm = (bid >> 1) * 4 + mw;
    const uint4* pAh = (const uint4*)gAh_f + (size_t)tbm * 4 * 32 + lane;
    const uint4* pAl = (const uint4*)gAl_f + (size_t)tbm * 4 * 32 + lane;
    const int nb0 = chalf * 8 + nw * 4;
    const uint2* pBh = (const uint2*)gBh_f + lane;
    const uint2* pBl = (const uint2*)gBl_f + lane;

#pragma unroll 1
    for (int p = 0; p < 16; p++) {
        float m[4][4];
#pragma unroll
        for (int nb = 0; nb < 4; nb++)
#pragma unroll
            for (int k = 0; k < 4; k++) m[nb][k] = 0.f;

#pragma unroll
        for (int kb = 0; kb < 4; kb++) {
            uint4 A0 = __ldg(pAh + (size_t)p * (NTB * 4 * 32) + kb * 32);
            uint4 A1 = __ldg(pAl + (size_t)p * (NTB * 4 * 32) + kb * 32);
            uint2 Bh[4], Bl[4];
#pragma unroll
            for (int nb = 0; nb < 4; nb++) {
                size_t bo = (size_t)((p * 4 + kb) * 16 + nb0 + nb) * 32;
                Bh[nb] = __ldg(pBh + bo);
                Bl[nb] = __ldg(pBl + bo);
            }
#pragma unroll
            for (int nb = 0; nb < 4; nb++) {
                mma16(m[nb], A0.x, A0.y, A0.z, A0.w, Bh[nb].x, Bh[nb].y);
                mma16(m[nb], A1.x, A1.y, A1.z, A1.w, Bh[nb].x, Bh[nb].y);
                mma16(m[nb], A0.x, A0.y, A0.z, A0.w, Bl[nb].x, Bl[nb].y);
            }
        }

        const int fi = p >> 2, fj = p & 3;
        const float a0i = cA0[fi], a1i = cA1[fi];
        const float a0j = cA0[fj], a1j = cA1[fj];
        float dq[4] = {a0i * a0j, a0i * a1j, a1i * a0j, a1i * a1j};
#pragma unroll
        for (int nb = 0; nb < 4; nb++)
#pragma unroll
            for (int k = 0; k < 4; k++) {
                float mm = m[nb][k];
#pragma unroll
                for (int q = 0; q < 4; q++) acc[q][nb * 4 + k] += dq[q] * mm;
            }
    }

    // ---- fused epilogue: LIF membrane + multi-threshold spike ----
    const float beta = *beta_p;
    const float omb = 1.f - beta;

#pragma unroll
    for (int nb = 0; nb < 4; nb++) {
#pragma unroll
        for (int cs = 0; cs < 2; cs++) {
            const int col = nw * 32 + nb * 8 + 2 * (lane & 3) + cs;
            const int co = chalf * 64 + col;
            const float invn = snorm[col];
            const float bb = sb[col];
#pragma unroll
            for (int rs = 0; rs < 2; rs++) {
                const int t = TB + mw * 16 + (lane >> 2) + rs * 8;
                const int n = t >> 10;
                const int tyy = (t >> 5) & 31;
                const int txx = t & 31;
                const int mi = nb * 4 + rs * 2 + cs;
                const int base0 = ((n * COUT + co) * HDIM + 2 * tyy) * WDIM + 2 * txx;
#pragma unroll
                for (int py = 0; py < 2; py++) {
                    const int idx = base0 + py * WDIM;
                    float2 mv = *(const float2*)(mem + idx);
                    float c0 = acc[py * 2 + 0][mi];
                    float c1 = acc[py * 2 + 1][mi];
                    float nm0 = mv.x * beta + c0 * omb;
                    float nm1 = mv.y * beta + c1 * omb;
                    float mt0 = nm0 * invn - bb;
                    float mt1 = nm1 * invn - bb;
                    float s0 = (float)((mt0 > 0.f) + (mt0 > 1.f) + (mt0 > 2.f) + (mt0 > 3.f));
                    float s1 = (float)((mt1 > 0.f) + (mt1 > 1.f) + (mt1 > 2.f) + (mt1 > 3.f));
                    float f0 = (s0 > 0.f) ? 0.f : nm0;
                    float f1 = (s1 > 0.f) ? 0.f : nm1;
                    *(float2*)(out + idx) = make_float2(s0, s1);
                    *(float2*)(out + FM_OFF + idx) = make_float2(f0, f1);
                }
            }
        }
    }
}

extern "C" void kernel_launch(void* const* d_in, const int* in_sizes, int n_in,
                              void* d_out, int out_size) {
    const float* x    = (const float*)d_in[0];
    const float* mem  = (const float*)d_in[1];
    const float* kern = (const float*)d_in[2];
    const float* beta = (const float*)d_in[3];
    const float* b    = (const float*)d_in[4];
    float* out = (float*)d_out;

    cudaFuncSetAttribute(prep_Xt, cudaFuncAttributeMaxDynamicSharedMemorySize,
                         XT_SMEM);

    prep_norm<<<1, 512>>>(kern);
    prep_Wt<<<32, 256>>>(kern);
    prep_Xt<<<2048, 512, XT_SMEM>>>(x);
    wino_gemm<<<1024, 256>>>(mem, beta, b, out);
}

// round 17
// speedup vs baseline: 1.1546x; 1.1546x over previous
#include <cuda_runtime.h>
#include <cuda_fp16.h>
#include <cstdint>

#define NB    32
#define CIN   64
#define COUT  128
#define HDIM  64
#define WDIM  64
#define EPSV  1e-8f
#define FM_OFF (NB * COUT * HDIM * WDIM)
#define NTILES 32768              // 32 n * 32 ty * 32 tx (2x2 output tiles)

// ---- scratch (static __device__, no allocations) ----
__device__ float g_inv_norm[COUT];
// A operand (input transform), fp16 hi + lo: [pos][tile][ci]
__device__ __align__(128) __half g_Xh[16][NTILES][64];
__device__ __align__(128) __half g_Xl[16][NTILES][64];
// B operand, MMA-fragment-packed: [pos][kb][n8blk][lane][4 halves]
__device__ __align__(128) __half gBh_f[16][4][16][32][4];
__device__ __align__(128) __half gBl_f[16][4][16][32][4];

// ---- helpers ----
__device__ __forceinline__ void cpa16(uint32_t dst, const void* src) {
    asm volatile("cp.async.ca.shared.global [%0], [%1], 16;" :: "r"(dst), "l"(src));
}
__device__ __forceinline__ void cpcommit() {
    asm volatile("cp.async.commit_group;" ::: "memory");
}
template <int N>
__device__ __forceinline__ void cpwait() {
    asm volatile("cp.async.wait_group %0;" :: "n"(N) : "memory");
}
__device__ __forceinline__ void ldsm_x4(uint32_t& r0, uint32_t& r1, uint32_t& r2,
                                        uint32_t& r3, uint32_t a) {
    asm volatile("ldmatrix.sync.aligned.m8n8.x4.shared.b16 {%0,%1,%2,%3}, [%4];"
                 : "=r"(r0), "=r"(r1), "=r"(r2), "=r"(r3) : "r"(a));
}
__device__ __forceinline__ void mma16(float* d, const uint32_t* a, uint32_t b0,
                                      uint32_t b1) {
    asm volatile(
        "mma.sync.aligned.m16n8k16.row.col.f32.f16.f16.f32 "
        "{%0,%1,%2,%3},{%4,%5,%6,%7},{%8,%9},{%0,%1,%2,%3};"
        : "+f"(d[0]), "+f"(d[1]), "+f"(d[2]), "+f"(d[3])
        : "r"(a[0]), "r"(a[1]), "r"(a[2]), "r"(a[3]), "r"(b0), "r"(b1));
}
// unscaled fp16 split (R16-verified numerics)
__device__ __forceinline__ void hsplit(float v, uint16_t& h, uint16_t& l) {
    __half hb = __float2half(v);
    __half lb = __float2half(v - __half2float(hb));
    h = __half_as_ushort(hb);
    l = __half_as_ushort(lb);
}

// output transform rows A^T = {{1,1,1,0},{0,1,-1,-1}}
__device__ const float cA0[4] = {1.f, 1.f, 1.f, 0.f};
__device__ const float cA1[4] = {0.f, 1.f, -1.f, -1.f};

// ---------- prep: per-Cout 1/(||k||^2 + eps) ----------
__global__ void prep_norm(const float* __restrict__ kern) {
    __shared__ float red[512];
    int t = threadIdx.x;
    int co = t & 127;
    int part = t >> 7;
    float s = 0.f;
#pragma unroll 4
    for (int i = part * 144; i < part * 144 + 144; i++) {
        float v = kern[i * COUT + co];
        s += v * v;
    }
    red[t] = s;
    __syncthreads();
    if (t < 128)
        g_inv_norm[co] = 1.f / (red[co] + red[co + 128] + red[co + 256] + red[co + 384] + EPSV);
}

// ---------- prep: weight transform W~ = G g G^T, fragment-packed fp16 hi/lo ----------
// (layout HW-verified in R16)
__global__ void prep_Wt(const float* __restrict__ kern) {
    int id = blockIdx.x * 256 + threadIdx.x;   // 8192
    int co = id & 127;
    int ci = id >> 7;

    float g[3][3];
#pragma unroll
    for (int kh = 0; kh < 3; kh++)
#pragma unroll
        for (int kw = 0; kw < 3; kw++)
            g[kh][kw] = kern[(kh * 3 + kw) * (CIN * COUT) + ci * COUT + co];

    float t[4][3];
#pragma unroll
    for (int kw = 0; kw < 3; kw++) {
        t[0][kw] = g[0][kw];
        t[1][kw] = 0.5f * (g[0][kw] + g[1][kw] + g[2][kw]);
        t[2][kw] = 0.5f * (g[0][kw] - g[1][kw] + g[2][kw]);
        t[3][kw] = g[2][kw];
    }
    const int kb = ci >> 4;
    const int ihalf = (ci >> 3) & 1;
    const int tig = (ci >> 1) & 3;
    const int lsb = ci & 1;
    const int L = (co & 7) * 4 + tig;
    const int nb = co >> 3;
#pragma unroll
    for (int i = 0; i < 4; i++) {
        float wv[4];
        wv[0] = t[i][0];
        wv[1] = 0.5f * (t[i][0] + t[i][1] + t[i][2]);
        wv[2] = 0.5f * (t[i][0] - t[i][1] + t[i][2]);
        wv[3] = t[i][2];
#pragma unroll
        for (int j = 0; j < 4; j++) {
            int p = i * 4 + j;
            uint16_t h, l;
            hsplit(wv[j], h, l);
            gBh_f[p][kb][nb][L][ihalf * 2 + lsb] = __ushort_as_half(h);
            gBl_f[p][kb][nb][L][ihalf * 2 + lsb] = __ushort_as_half(l);
        }
    }
}

// ---------- prep: input transform X~ = B^T d B, smem-staged (R11 structure) ----------
#define XSP 66
#define XT_SMEM (4 * 64 * XSP * 4)
__global__ __launch_bounds__(256)
void prep_Xt(const float* __restrict__ x) {
    extern __shared__ float xs[];
    const int n = blockIdx.x >> 5;
    const int ty = blockIdx.x & 31;
    const int tid = threadIdx.x;
    const int w = tid >> 5;           // warp: 4 tx tiles
    const int l = tid & 31;           // ci pair

#pragma unroll
    for (int i = 0; i < 64; i++) {
        int idx = tid + i * 256;      // 16384 = 64ci * 4r * 64c
        int ci = idx >> 8;
        int rem = idx & 255;
        int r = rem >> 6;
        int c = rem & 63;
        int gr = 2 * ty - 1 + r;
        float v = (gr >= 0 && gr < HDIM)
                      ? __ldg(x + ((n * CIN + ci) * HDIM + gr) * WDIM + c)
                      : 0.f;
        xs[(r * 64 + c) * XSP + ci] = v;
    }
    __syncthreads();

#pragma unroll 1
    for (int t = 0; t < 4; t++) {
        const int tx = w * 4 + t;
        const int tile = n * 1024 + ty * 32 + tx;
        const int wb = 2 * tx - 1;

        float2 d2[4][4];
#pragma unroll
        for (int c = 0; c < 4; c++) {
            int gc = wb + c;
            bool ok = (gc >= 0) & (gc < WDIM);
#pragma unroll
            for (int r = 0; r < 4; r++) {
                d2[r][c] = ok ? *(const float2*)&xs[(r * 64 + gc) * XSP + 2 * l]
                              : make_float2(0.f, 0.f);
            }
        }

        uint32_t hv[16], lv[16];
#pragma unroll
        for (int cc = 0; cc < 2; cc++) {
            float d[4][4];
#pragma unroll
            for (int r = 0; r < 4; r++)
#pragma unroll
                for (int c = 0; c < 4; c++)
                    d[r][c] = cc ? d2[r][c].y : d2[r][c].x;

            float s[4][4];
#pragma unroll
            for (int c = 0; c < 4; c++) {
                s[0][c] = d[0][c] - d[2][c];
                s[1][c] = d[1][c] + d[2][c];
                s[2][c] = d[2][c] - d[1][c];
                s[3][c] = d[1][c] - d[3][c];
            }
#pragma unroll
            for (int i = 0; i < 4; i++) {
                float vv[4];
                vv[0] = s[i][0] - s[i][2];
                vv[1] = s[i][1] + s[i][2];
                vv[2] = s[i][2] - s[i][1];
                vv[3] = s[i][1] - s[i][3];
#pragma unroll
                for (int j = 0; j < 4; j++) {
                    int p = i * 4 + j;
                    uint16_t h, lo;
                    hsplit(vv[j], h, lo);
                    if (cc == 0) {
                        hv[p] = (uint32_t)h;
                        lv[p] = (uint32_t)lo;
                    } else {
                        hv[p] |= (uint32_t)h << 16;
                        lv[p] |= (uint32_t)lo << 16;
                    }
                }
            }
        }
#pragma unroll
        for (int p = 0; p < 16; p++) {
            ((uint32_t*)g_Xh[p][tile])[l] = hv[p];
            ((uint32_t*)g_Xl[p][tile])[l] = lv[p];
        }
    }
}

// ---------- main: hybrid Winograd GEMM — cp.async A + fragment-direct B ----------
// smem per buffer: Ah +0 (64 rows x 144B), Al +9216; BUFB = 18432, x2 buffers.
#define A_PL   9216
#define BUFB   18432
#define NORMF  (2 * BUFB / 4)           // float index 9216
#define BIASF  (NORMF + 64)
#define SMEM_BYTES (2 * BUFB + 512)

__global__ __launch_bounds__(256, 2)
void wino_gemm(const float* __restrict__ mem, const float* __restrict__ beta_p,
               const float* __restrict__ b_p, float* __restrict__ out) {
    extern __shared__ char smc[];
    float* smf = (float*)smc;
    const uint32_t smu = (uint32_t)__cvta_generic_to_shared(smc);

    const int tid = threadIdx.x;
    const int lane = tid & 31;
    const int wrp = tid >> 5;
    const int mw = wrp & 3;           // M-warp: tiles mw*16..+15
    const int nw = wrp >> 2;          // N-warp: co nw*32..+31
    const int bid = blockIdx.x;
    const int chalf = bid & 1;
    const int TB = (bid >> 1) * 64;   // base tile

    if (tid < 64) {
        smf[NORMF + tid] = g_inv_norm[chalf * 64 + tid];
        smf[BIASF + tid] = b_p[chalf * 64 + tid];
    }

    // A-only staging: 1024 chunks (2 planes x 64 rows x 8)
#define STAGE(p, buf)                                                         \
    {                                                                         \
        const int pp = (p);                                                   \
        uint32_t base = smu + (buf)*BUFB;                                     \
        _Pragma("unroll")                                                     \
        for (int i = 0; i < 4; i++) {                                         \
            int idx = tid + i * 256;                                          \
            int pl = idx >> 9;                                                \
            int q = idx & 511;                                                \
            int row = q >> 3, c = q & 7;                                      \
            cpa16(base + pl * A_PL + row * 144 + c * 16,                      \
                  (pl ? g_Xl[pp][TB + row] : g_Xh[pp][TB + row]) + c * 8);    \
        }                                                                     \
    }

    float acc[4][16];
#pragma unroll
    for (int q = 0; q < 4; q++)
#pragma unroll
        for (int i = 0; i < 16; i++) acc[q][i] = 0.f;

    const uint32_t arow_off =
        (uint32_t)(mw * 16 + (lane & 15)) * 144 + (uint32_t)((lane >> 4) * 8) * 2;
    const int nb0 = chalf * 8 + nw * 4;
    const uint2* pBh = (const uint2*)gBh_f + lane;
    const uint2* pBl = (const uint2*)gBl_f + lane;

    STAGE(0, 0);
    cpcommit();

#pragma unroll 1
    for (int p = 0; p < 16; p++) {
        const int buf = p & 1;
        cpwait<0>();
        __syncthreads();
        if (p < 15) {
            STAGE(p + 1, buf ^ 1);
            cpcommit();
        }

        const uint32_t Ab = smu + buf * BUFB;
        float m[4][4];
#pragma unroll
        for (int nb = 0; nb < 4; nb++)
#pragma unroll
            for (int k = 0; k < 4; k++) m[nb][k] = 0.f;

#pragma unroll
        for (int kb = 0; kb < 4; kb++) {
            // B fragments (L2-resident) — issue first to overlap latency
            uint2 Bh[4], Bl[4];
#pragma unroll
            for (int nb = 0; nb < 4; nb++) {
                size_t bo = (size_t)((p * 4 + kb) * 16 + nb0 + nb) * 32;
                Bh[nb] = __ldg(pBh + bo);
                Bl[nb] = __ldg(pBl + bo);
            }
            uint32_t aAddr = Ab + arow_off + kb * 32;
            uint32_t ah[4], al[4];
            ldsm_x4(ah[0], ah[1], ah[2], ah[3], aAddr);
            ldsm_x4(al[0], al[1], al[2], al[3], aAddr + A_PL);
#pragma unroll
            for (int nb = 0; nb < 4; nb++) {
                mma16(m[nb], ah, Bh[nb].x, Bh[nb].y);
                mma16(m[nb], al, Bh[nb].x, Bh[nb].y);
                mma16(m[nb], ah, Bl[nb].x, Bl[nb].y);
            }
        }

        // fold: acc[pyx] += AT[py][fi]*AT[px][fj] * m
        const int fi = p >> 2, fj = p & 3;
        const float a0i = cA0[fi], a1i = cA1[fi];
        const float a0j = cA0[fj], a1j = cA1[fj];
        float dq[4] = {a0i * a0j, a0i * a1j, a1i * a0j, a1i * a1j};
#pragma unroll
        for (int nb = 0; nb < 4; nb++)
#pragma unroll
            for (int k = 0; k < 4; k++) {
                float mm = m[nb][k];
#pragma unroll
                for (int q = 0; q < 4; q++) acc[q][nb * 4 + k] += dq[q] * mm;
            }
    }

    // ---- fused epilogue: LIF membrane + multi-threshold spike ----
    const float beta = *beta_p;
    const float omb = 1.f - beta;

#pragma unroll
    for (int nb = 0; nb < 4; nb++) {
#pragma unroll
        for (int cs = 0; cs < 2; cs++) {
            const int col = nw * 32 + nb * 8 + 2 * (lane & 3) + cs;
            const int co = chalf * 64 + col;
            const float invn = smf[NORMF + col];
            const float bb = smf[BIASF + col];
#pragma unroll
            for (int rs = 0; rs < 2; rs++) {
                const int t = TB + mw * 16 + (lane >> 2) + rs * 8;
                const int n = t >> 10;
                const int tyy = (t >> 5) & 31;
                const int txx = t & 31;
                const int mi = nb * 4 + rs * 2 + cs;
                const int base0 = ((n * COUT + co) * HDIM + 2 * tyy) * WDIM + 2 * txx;
#pragma unroll
                for (int py = 0; py < 2; py++) {
                    const int idx = base0 + py * WDIM;
                    float2 mv = *(const float2*)(mem + idx);
                    float c0 = acc[py * 2 + 0][mi];
                    float c1 = acc[py * 2 + 1][mi];
                    float nm0 = mv.x * beta + c0 * omb;
                    float nm1 = mv.y * beta + c1 * omb;
                    float mt0 = nm0 * invn - bb;
                    float mt1 = nm1 * invn - bb;
                    float s0 = (float)((mt0 > 0.f) + (mt0 > 1.f) + (mt0 > 2.f) + (mt0 > 3.f));
                    float s1 = (float)((mt1 > 0.f) + (mt1 > 1.f) + (mt1 > 2.f) + (mt1 > 3.f));
                    float f0 = (s0 > 0.f) ? 0.f : nm0;
                    float f1 = (s1 > 0.f) ? 0.f : nm1;
                    *(float2*)(out + idx) = make_float2(s0, s1);
                    *(float2*)(out + FM_OFF + idx) = make_float2(f0, f1);
                }
            }
        }
    }
}

extern "C" void kernel_launch(void* const* d_in, const int* in_sizes, int n_in,
                              void* d_out, int out_size) {
    const float* x    = (const float*)d_in[0];
    const float* mem  = (const float*)d_in[1];
    const float* kern = (const float*)d_in[2];
    const float* beta = (const float*)d_in[3];
    const float* b    = (const float*)d_in[4];
    float* out = (float*)d_out;

    cudaFuncSetAttribute(wino_gemm, cudaFuncAttributeMaxDynamicSharedMemorySize,
                         SMEM_BYTES);
    cudaFuncSetAttribute(prep_Xt, cudaFuncAttributeMaxDynamicSharedMemorySize,
                         XT_SMEM);

    prep_norm<<<1, 512>>>(kern);
    prep_Wt<<<32, 256>>>(kern);
    prep_Xt<<<1024, 256, XT_SMEM>>>(x);
    wino_gemm<<<1024, 256, SMEM_BYTES>>>(mem, beta, b, out);
}